// round 11
// baseline (speedup 1.0000x reference)
#include <cuda_runtime.h>
#include <cuda_bf16.h>
#include <math.h>
#include <stdint.h>

// ---------------------------------------------------------------------------
// Problem constants
// ---------------------------------------------------------------------------
#define BB    2
#define SSEQ  1024
#define DDIM  1024
#define HHH   16
#define DKV   64
#define DHH   4096
#define LLAY  8
#define VVOC  256
#define MM    (BB*SSEQ)        // 2048
#define NQKV  3072

// ---------------------------------------------------------------------------
// Scratch (device globals: allocation-free)
// ---------------------------------------------------------------------------
__device__ float g_x[MM*DDIM];
__device__ float g_o[MM*DDIM];
__device__ float g_h[MM*DDIM];
__device__ float g_t[MM*DHH];
__device__ __nv_bfloat16 g_qkvhi[MM*NQKV], g_qkvlo[MM*NQKV];

// fp32 transposed weights (intermediate)
__device__ float g_WqkvT[LLAY*NQKV*DDIM];
__device__ float g_WoT  [LLAY*DDIM*DDIM];
__device__ float g_W1T  [LLAY*DHH*DDIM];
__device__ float g_W2T  [LLAY*DDIM*DHH];
__device__ float g_WrT  [VVOC*DDIM];
__device__ float g_bqkv [LLAY*NQKV];

// int8 limb planes + scales: weights
__device__ int8_t g_Wqkv0[LLAY*NQKV*DDIM], g_Wqkv1[LLAY*NQKV*DDIM];
__device__ int8_t g_Wo0[LLAY*DDIM*DDIM],   g_Wo1[LLAY*DDIM*DDIM];
__device__ int8_t g_W10[LLAY*DHH*DDIM],    g_W11[LLAY*DHH*DDIM];
__device__ int8_t g_W20[LLAY*DDIM*DHH],    g_W21[LLAY*DDIM*DHH];
__device__ int8_t g_Wr0[VVOC*DDIM],        g_Wr1[VVOC*DDIM];
__device__ float  g_sWqkv[LLAY*NQKV], g_sWo[LLAY*DDIM], g_sW1[LLAY*DHH];
__device__ float  g_sW2[LLAY*DDIM],   g_sWr[VVOC];

// int8 limb planes + scales: activations
__device__ int8_t g_xq0[MM*DDIM], g_xq1[MM*DDIM];
__device__ int8_t g_oq0[MM*DDIM], g_oq1[MM*DDIM];
__device__ int8_t g_hq0[MM*DDIM], g_hq1[MM*DDIM];
__device__ int8_t g_tq0[MM*DHH],  g_tq1[MM*DHH];
__device__ float  g_sx[MM], g_so[MM], g_sh[MM], g_st[MM];

// ---------------------------------------------------------------------------
// Helpers
// ---------------------------------------------------------------------------
__device__ __forceinline__ uint32_t smem_u32(const void* p) {
    uint32_t a;
    asm("{ .reg .u64 t; cvta.to.shared.u64 t, %1; cvt.u32.u64 %0, t; }"
        : "=r"(a) : "l"(p));
    return a;
}

__device__ __forceinline__ void ldmx4(uint32_t* r, uint32_t addr) {
    asm volatile("ldmatrix.sync.aligned.m8n8.x4.shared.b16 {%0,%1,%2,%3}, [%4];"
        : "=r"(r[0]), "=r"(r[1]), "=r"(r[2]), "=r"(r[3]) : "r"(addr));
}

__device__ __forceinline__ void ldmx4t(uint32_t* r, uint32_t addr) {
    asm volatile("ldmatrix.sync.aligned.m8n8.x4.trans.shared.b16 {%0,%1,%2,%3}, [%4];"
        : "=r"(r[0]), "=r"(r[1]), "=r"(r[2]), "=r"(r[3]) : "r"(addr));
}

// bf16 inputs, f32 acc (attention)
__device__ __forceinline__ void mma16816(float* d, const uint32_t* a,
                                         uint32_t b0, uint32_t b1) {
    asm volatile("mma.sync.aligned.m16n8k16.row.col.f32.bf16.bf16.f32 "
        "{%0,%1,%2,%3}, {%4,%5,%6,%7}, {%8,%9}, {%0,%1,%2,%3};"
        : "+f"(d[0]), "+f"(d[1]), "+f"(d[2]), "+f"(d[3])
        : "r"(a[0]), "r"(a[1]), "r"(a[2]), "r"(a[3]), "r"(b0), "r"(b1));
}

// s8 inputs, s32 acc (GEMM)
__device__ __forceinline__ void imma16832(int* d, const uint32_t* a,
                                          uint32_t b0, uint32_t b1) {
    asm volatile("mma.sync.aligned.m16n8k32.row.col.s32.s8.s8.s32 "
        "{%0,%1,%2,%3}, {%4,%5,%6,%7}, {%8,%9}, {%0,%1,%2,%3};"
        : "+r"(d[0]), "+r"(d[1]), "+r"(d[2]), "+r"(d[3])
        : "r"(a[0]), "r"(a[1]), "r"(a[2]), "r"(a[3]), "r"(b0), "r"(b1));
}

__device__ __forceinline__ void cp16(uint32_t dst, const void* src) {
    asm volatile("cp.async.cg.shared.global [%0], [%1], 16;"
        :: "r"(dst), "l"(src) : "memory");
}
#define CP_COMMIT() asm volatile("cp.async.commit_group;" ::: "memory")
#define CP_WAIT0()  asm volatile("cp.async.wait_group 0;" ::: "memory")
#define CP_WAIT1()  asm volatile("cp.async.wait_group 1;" ::: "memory")

__device__ __forceinline__ float gelu_exact(float v) {
    return 0.5f * v * (1.0f + erff(v * 0.70710678118654752f));
}

__device__ __forceinline__ void split1(float v, __nv_bfloat16& hi, __nv_bfloat16& lo) {
    hi = __float2bfloat16(v);
    lo = __float2bfloat16(v - __bfloat162float(hi));
}

// ---------------------------------------------------------------------------
// int8 GEMM: C = act( sA*sB*(A@Bt^T) + bias ) + res
// A,B as 2 int8 limb planes [rows,K] K-major; D = sA sB (acc0 + acc1/128).
// BM in {128,64}, BN=128, BK=64; 8 warps (2x4); 3-stage cp.async pipeline.
// ---------------------------------------------------------------------------
#define LDQ 80

template<int BM, int MINB>
__global__ void __launch_bounds__(256, MINB)
gemm_s8(const int8_t* __restrict__ A0, const int8_t* __restrict__ A1,
        const int8_t* __restrict__ B0, const int8_t* __restrict__ B1,
        const float* __restrict__ sA, const float* __restrict__ sB,
        const float* __restrict__ bias, const float* __restrict__ res,
        float* __restrict__ Cf,
        __nv_bfloat16* __restrict__ Chi, __nv_bfloat16* __restrict__ Clo,
        int M, int N, int K, int gelu)
{
    constexpr int MT     = BM / 32;
    constexpr int ROWS   = 2 * BM + 256;
    constexpr int STAGE  = ROWS * LDQ;
    constexpr int OFF_A1 = BM * LDQ;
    constexpr int OFF_B0 = 2 * BM * LDQ;
    constexpr int OFF_B1 = (2 * BM + 128) * LDQ;
    constexpr int NST    = 3;

    extern __shared__ char sm[];
    const uint32_t smb = smem_u32(sm);

    const int tid  = threadIdx.x;
    const int lane = tid & 31;
    const int wid  = tid >> 5;
    const int wr   = wid >> 2;
    const int wc   = wid & 3;
    const int m0   = blockIdx.y * BM;
    const int n0   = blockIdx.x * 128;

    const int nIt = K >> 6;

    auto issue = [&](int it) {
        const uint32_t sp = smb + (uint32_t)((it % NST) * STAGE);
        const int koff = it * 64;
#pragma unroll
        for (int s = 0; s < ROWS / 64; s++) {
            const int c   = tid + s * 256;
            const int row = c >> 2;
            const int ch  = c & 3;
            const int8_t* g;
            if (row < BM)                g = A0 + (size_t)(m0 + row) * K;
            else if (row < 2 * BM)       g = A1 + (size_t)(m0 + row - BM) * K;
            else if (row < 2 * BM + 128) g = B0 + (size_t)(n0 + row - 2 * BM) * K;
            else                         g = B1 + (size_t)(n0 + row - 2 * BM - 128) * K;
            cp16(sp + (uint32_t)(row * LDQ + ch * 16), g + koff + ch * 16);
        }
        CP_COMMIT();
    };

    int acc0[MT][4][4], acc1[MT][4][4];
#pragma unroll
    for (int i = 0; i < MT; i++)
#pragma unroll
        for (int j = 0; j < 4; j++)
#pragma unroll
            for (int q = 0; q < 4; q++) { acc0[i][j][q] = 0; acc1[i][j][q] = 0; }

    issue(0);
    issue(1);

    for (int it = 0; it < nIt; ++it) {
        if (it + 1 < nIt) { CP_WAIT1(); } else { CP_WAIT0(); }
        __syncthreads();
        if (it + 2 < nIt) issue(it + 2);

        const uint32_t stage = smb + (uint32_t)((it % NST) * STAGE);
        const uint32_t aB = stage
            + (uint32_t)((wr * (BM/2) + (lane & 15)) * LDQ + (lane >> 4) * 16);
        const uint32_t bB = stage + OFF_B0 + (uint32_t)((wc * 32 + lane) * LDQ);

#pragma unroll
        for (int kc = 0; kc < 2; kc++) {
            uint32_t a0[MT][4], a1[MT][4];
            uint32_t b00[4], b01[4], b10[4], b11[4];
#pragma unroll
            for (int mt = 0; mt < MT; mt++) {
                ldmx4(a0[mt], aB + mt * 16 * LDQ + kc * 32);
                ldmx4(a1[mt], aB + OFF_A1 + mt * 16 * LDQ + kc * 32);
            }
            ldmx4(b00, bB + kc * 32);
            ldmx4(b01, bB + kc * 32 + 16);
            ldmx4(b10, bB + (OFF_B1 - OFF_B0) + kc * 32);
            ldmx4(b11, bB + (OFF_B1 - OFF_B0) + kc * 32 + 16);

#pragma unroll
            for (int mt = 0; mt < MT; mt++)
#pragma unroll
                for (int nt = 0; nt < 4; nt++)
                    imma16832(acc0[mt][nt], a0[mt], b00[nt], b01[nt]);
#pragma unroll
            for (int mt = 0; mt < MT; mt++)
#pragma unroll
                for (int nt = 0; nt < 4; nt++)
                    imma16832(acc1[mt][nt], a0[mt], b10[nt], b11[nt]);
#pragma unroll
            for (int mt = 0; mt < MT; mt++)
#pragma unroll
                for (int nt = 0; nt < 4; nt++)
                    imma16832(acc1[mt][nt], a1[mt], b00[nt], b01[nt]);
        }
    }

    // ---- epilogue ----
    const int er = m0 + wr * (BM/2) + (lane >> 2);
    const int ec = n0 + wc * 32 + (lane & 3) * 2;
#pragma unroll
    for (int mt = 0; mt < MT; mt++) {
#pragma unroll
        for (int half = 0; half < 2; half++) {
            const int row = er + mt * 16 + half * 8;
            const float sa = sA[row];
            const size_t rb2 = (size_t)row * N;
            const float* rrow = res ? res + rb2 : nullptr;
#pragma unroll
            for (int nt = 0; nt < 4; nt++) {
                const int col = ec + nt * 8;
                const float s0 = sa * sB[col];
                const float s1 = sa * sB[col + 1];
                float v0 = s0 * ((float)acc0[mt][nt][half*2+0]
                               + (float)acc1[mt][nt][half*2+0] * 0.0078125f);
                float v1 = s1 * ((float)acc0[mt][nt][half*2+1]
                               + (float)acc1[mt][nt][half*2+1] * 0.0078125f);
                if (bias) { v0 += bias[col]; v1 += bias[col + 1]; }
                if (gelu) { v0 = gelu_exact(v0); v1 = gelu_exact(v1); }
                if (rrow) { v0 += rrow[col]; v1 += rrow[col + 1]; }
                if (Cf) *(float2*)(Cf + rb2 + col) = make_float2(v0, v1);
                if (Chi) {
                    __nv_bfloat16 h0, l0, h1, l1;
                    split1(v0, h0, l0);
                    split1(v1, h1, l1);
                    *(__nv_bfloat162*)(Chi + rb2 + col) = __nv_bfloat162(h0, h1);
                    *(__nv_bfloat162*)(Clo + rb2 + col) = __nv_bfloat162(l0, l1);
                }
            }
        }
    }
}

// ---------------------------------------------------------------------------
// Row quantizer: fp32 [rows, cols] -> int8 limbs + per-row scale
// ---------------------------------------------------------------------------
__global__ void quant_rows(const float* __restrict__ src,
                           int8_t* __restrict__ q0, int8_t* __restrict__ q1,
                           float* __restrict__ sc, int cols)
{
    const int row = blockIdx.x;
    const float* r = src + (size_t)row * cols;
    const int tid = threadIdx.x;

    float am = 0.0f;
    for (int c = tid * 4; c < cols; c += 1024) {
        float4 v = *(const float4*)(r + c);
        am = fmaxf(am, fmaxf(fmaxf(fabsf(v.x), fabsf(v.y)),
                             fmaxf(fabsf(v.z), fabsf(v.w))));
    }
    __shared__ float red[32];
#pragma unroll
    for (int o = 16; o; o >>= 1) am = fmaxf(am, __shfl_xor_sync(0xffffffffu, am, o));
    if ((tid & 31) == 0) red[tid >> 5] = am;
    __syncthreads();
    if (tid < 32) {
        float v = (tid < 8) ? red[tid] : 0.0f;
#pragma unroll
        for (int o = 4; o; o >>= 1) v = fmaxf(v, __shfl_xor_sync(0xffffffffu, v, o));
        if (tid == 0) red[0] = v;
    }
    __syncthreads();
    const float amax = red[0];
    const float s = fmaxf(amax, 1e-20f) * (1.0f / 127.0f);
    const float inv = 1.0f / s;
    if (tid == 0) sc[row] = s;

    for (int c = tid * 4; c < cols; c += 1024) {
        float4 v = *(const float4*)(r + c);
        char4 c0, c1;
        float q; int i0, i1; float rr;
        q = v.x * inv; i0 = __float2int_rn(q); rr = q - i0;
        i1 = __float2int_rn(rr * 128.0f); c0.x = (char)i0; c1.x = (char)i1;
        q = v.y * inv; i0 = __float2int_rn(q); rr = q - i0;
        i1 = __float2int_rn(rr * 128.0f); c0.y = (char)i0; c1.y = (char)i1;
        q = v.z * inv; i0 = __float2int_rn(q); rr = q - i0;
        i1 = __float2int_rn(rr * 128.0f); c0.z = (char)i0; c1.z = (char)i1;
        q = v.w * inv; i0 = __float2int_rn(q); rr = q - i0;
        i1 = __float2int_rn(rr * 128.0f); c0.w = (char)i0; c1.w = (char)i1;
        *(char4*)(q0 + (size_t)row * cols + c) = c0;
        *(char4*)(q1 + (size_t)row * cols + c) = c1;
    }
}

// ---------------------------------------------------------------------------
// Batched transposes (fp32)
// ---------------------------------------------------------------------------
__global__ void tr_qkv3(const float* __restrict__ Wq, const float* __restrict__ Wk,
                        const float* __restrict__ Wv, float* __restrict__ dst,
                        int l0)
{
    __shared__ float t[32][33];
    const int z = blockIdx.z;
    const int l = l0 + z / 3;
    const int which = z % 3;
    const float* src = (which == 0 ? Wq : which == 1 ? Wk : Wv)
                     + (size_t)l * DDIM * DDIM;
    float* d = dst + (size_t)l * NQKV * DDIM + (size_t)which * DDIM * DDIM;
    const int k0 = blockIdx.y * 32, n0 = blockIdx.x * 32;
    const int tx = threadIdx.x, ty = threadIdx.y;
#pragma unroll
    for (int i = 0; i < 32; i += 8)
        t[ty + i][tx] = src[(size_t)(k0 + ty + i) * DDIM + n0 + tx];
    __syncthreads();
#pragma unroll
    for (int i = 0; i < 32; i += 8)
        d[(size_t)(n0 + ty + i) * DDIM + k0 + tx] = t[tx][ty + i];
}

__global__ void transpose_b(const float* __restrict__ src, float* __restrict__ dst,
                            int K, int N, size_t sstr, size_t dstr)
{
    __shared__ float t[32][33];
    const int l = blockIdx.z;
    src += (size_t)l * sstr;
    dst += (size_t)l * dstr;
    const int k0 = blockIdx.y * 32, n0 = blockIdx.x * 32;
    const int tx = threadIdx.x, ty = threadIdx.y;
#pragma unroll
    for (int i = 0; i < 32; i += 8)
        t[ty + i][tx] = src[(size_t)(k0 + ty + i) * N + n0 + tx];
    __syncthreads();
#pragma unroll
    for (int i = 0; i < 32; i += 8)
        dst[(size_t)(n0 + ty + i) * K + k0 + tx] = t[tx][ty + i];
}

// ---------------------------------------------------------------------------
// Fused embedding + bias concat
// ---------------------------------------------------------------------------
__global__ void embed_bias(const int* __restrict__ tokens,
                           const float* __restrict__ emb,
                           const float* __restrict__ pos,
                           float* __restrict__ x,
                           const float* __restrict__ bq, const float* __restrict__ bk,
                           const float* __restrict__ bv, float* __restrict__ bqkv)
{
    if (blockIdx.x < MM) {
        int i = blockIdx.x;
        int s = i & (SSEQ - 1);
        int t = tokens[i];
        const float4* e4 = (const float4*)(emb + (size_t)t * DDIM);
        const float4* p4 = (const float4*)(pos + (size_t)s * DDIM);
        float4*       x4 = (float4*)(x + (size_t)i * DDIM);
        int d = threadIdx.x;
        float4 a = e4[d], b = p4[d];
        x4[d] = make_float4(a.x + b.x, a.y + b.y, a.z + b.z, a.w + b.w);
    } else {
        int e = (blockIdx.x - MM) * 256 + threadIdx.x;
        int l = e / NQKV;
        int i = e - l * NQKV;
        float v;
        if (i < 1024)       v = bq[l * DDIM + i];
        else if (i < 2048)  v = bk[l * DDIM + i - 1024];
        else                v = bv[l * DDIM + i - 2048];
        bqkv[e] = v;
    }
}

// ---------------------------------------------------------------------------
// Tensor-core flash attention (R10-proven, bf16x3), fp32 output
// ---------------------------------------------------------------------------
#define ALDB  144
#define AQHI  0
#define AQLO  18432
#define AKHI  36864
#define AARR  9216
#define ASMEM 73728

__global__ void __launch_bounds__(256, 2)
attn_mma(const __nv_bfloat16* __restrict__ qkvhi,
         const __nv_bfloat16* __restrict__ qkvlo,
         float* __restrict__ o)
{
    extern __shared__ char sm[];
    const uint32_t smb = smem_u32(sm);

    const int tid  = threadIdx.x;
    const int lane = tid & 31;
    const int w    = tid >> 5;
    const int qb   = blockIdx.x;
    const int bh   = blockIdx.y;
    const int b    = bh >> 4;
    const int h    = bh & 15;
    const int rowbase = b * SSEQ;
    const int qc = h * DKV, kc = 1024 + h * DKV, vc = 2048 + h * DKV;

    {
        const int ch  = tid & 7;
        const int wh  = (tid >> 3) & 1;
        const __nv_bfloat16* src = (wh ? qkvlo : qkvhi);
        const uint32_t dstb = smb + (wh ? AQLO : AQHI) + ch * 16;
#pragma unroll
        for (int i = 0; i < 8; i++) {
            const int r = i * 16 + (tid >> 4);
            cp16(dstb + r * ALDB,
                 src + (size_t)(rowbase + qb * 128 + r) * NQKV + qc + ch * 8);
        }
        CP_COMMIT();
    }

    float sO[8][4];
#pragma unroll
    for (int i = 0; i < 8; i++)
#pragma unroll
        for (int q = 0; q < 4; q++) sO[i][q] = 0.0f;
    float mrow[2] = { -INFINITY, -INFINITY };
    float lrow[2] = { 0.0f, 0.0f };

    const int ch  = tid & 7;
    const int arr = (tid >> 3) & 3;
    const __nv_bfloat16* kvsrc =
        (arr == 0) ? qkvhi : (arr == 1) ? qkvlo : (arr == 2) ? qkvhi : qkvlo;
    const int kvcol = (arr < 2) ? kc : vc;
    const uint32_t kvdstb = smb + AKHI + arr * AARR + ch * 16;

    const int ntile = 2 * (qb + 1);
    for (int kt = 0; kt < ntile; kt++) {
        __syncthreads();
        {
#pragma unroll
            for (int i = 0; i < 8; i++) {
                const int r = i * 8 + (tid >> 5);
                cp16(kvdstb + r * ALDB,
                     kvsrc + (size_t)(rowbase + kt * 64 + r) * NQKV + kvcol + ch * 8);
            }
            CP_COMMIT();
        }
        CP_WAIT0();
        __syncthreads();

        float s[8][4];
#pragma unroll
        for (int i = 0; i < 8; i++)
#pragma unroll
            for (int q = 0; q < 4; q++) s[i][q] = 0.0f;

        const uint32_t qHiB = smb + AQHI
            + (uint32_t)((w * 16 + (lane & 15)) * ALDB + (lane >> 4) * 16);
        const uint32_t kHiB0 = smb + AKHI + (uint32_t)(lane * ALDB);

#pragma unroll
        for (int ks = 0; ks < 4; ks++) {
            uint32_t aH[4], aL[4];
            ldmx4(aH, qHiB + ks * 32);
            ldmx4(aL, qHiB + (AQLO - AQHI) + ks * 32);
#pragma unroll
            for (int nb = 0; nb < 2; nb++) {
                const uint32_t kb = kHiB0 + nb * 32 * ALDB + ks * 32;
                uint32_t bh0[4], bh1[4], bl0[4], bl1[4];
                ldmx4(bh0, kb);
                ldmx4(bh1, kb + 16);
                ldmx4(bl0, kb + AARR);
                ldmx4(bl1, kb + AARR + 16);
#pragma unroll
                for (int nt = 0; nt < 4; nt++)
                    mma16816(s[nb * 4 + nt], aH, bh0[nt], bh1[nt]);
#pragma unroll
                for (int nt = 0; nt < 4; nt++)
                    mma16816(s[nb * 4 + nt], aH, bl0[nt], bl1[nt]);
#pragma unroll
                for (int nt = 0; nt < 4; nt++)
                    mma16816(s[nb * 4 + nt], aL, bh0[nt], bh1[nt]);
            }
        }

        const int r0 = qb * 128 + w * 16 + (lane >> 2);
        const int c0 = kt * 64 + (lane & 3) * 2;
#pragma unroll
        for (int nf = 0; nf < 8; nf++) {
            const int col = c0 + nf * 8;
#pragma unroll
            for (int q = 0; q < 4; q++) {
                const int row = r0 + (q >> 1) * 8;
                const int cc  = col + (q & 1);
                float v = s[nf][q] * 0.125f;
                s[nf][q] = (cc > row) ? -INFINITY : v;
            }
        }

        float mx0 = s[0][0], mx1 = s[0][2];
#pragma unroll
        for (int nf = 0; nf < 8; nf++) {
            mx0 = fmaxf(mx0, fmaxf(s[nf][0], s[nf][1]));
            mx1 = fmaxf(mx1, fmaxf(s[nf][2], s[nf][3]));
        }
        mx0 = fmaxf(mx0, __shfl_xor_sync(0xffffffffu, mx0, 1));
        mx0 = fmaxf(mx0, __shfl_xor_sync(0xffffffffu, mx0, 2));
        mx1 = fmaxf(mx1, __shfl_xor_sync(0xffffffffu, mx1, 1));
        mx1 = fmaxf(mx1, __shfl_xor_sync(0xffffffffu, mx1, 2));

        const float mn0 = fmaxf(mrow[0], mx0);
        const float mn1 = fmaxf(mrow[1], mx1);
        const float co0 = __expf(mrow[0] - mn0);
        const float co1 = __expf(mrow[1] - mn1);
        lrow[0] *= co0; lrow[1] *= co1;
#pragma unroll
        for (int nf = 0; nf < 8; nf++) {
            sO[nf][0] *= co0; sO[nf][1] *= co0;
            sO[nf][2] *= co1; sO[nf][3] *= co1;
        }
        float su0 = 0.0f, su1 = 0.0f;
#pragma unroll
        for (int nf = 0; nf < 8; nf++) {
            s[nf][0] = __expf(s[nf][0] - mn0); su0 += s[nf][0];
            s[nf][1] = __expf(s[nf][1] - mn0); su0 += s[nf][1];
            s[nf][2] = __expf(s[nf][2] - mn1); su1 += s[nf][2];
            s[nf][3] = __expf(s[nf][3] - mn1); su1 += s[nf][3];
        }
        su0 += __shfl_xor_sync(0xffffffffu, su0, 1);
        su0 += __shfl_xor_sync(0xffffffffu, su0, 2);
        su1 += __shfl_xor_sync(0xffffffffu, su1, 1);
        su1 += __shfl_xor_sync(0xffffffffu, su1, 2);
        lrow[0] += su0; lrow[1] += su1;
        mrow[0] = mn0; mrow[1] = mn1;

        const uint32_t vHiB0 = smb + AKHI + 2 * AARR
            + (uint32_t)((lane & 15) * ALDB + (lane >> 4) * 16);
#pragma unroll
        for (int ks = 0; ks < 4; ks++) {
            uint32_t pa_h[4], pa_l[4];
            {
                __nv_bfloat16 h0, l0, h1, l1;
                split1(s[2*ks][0], h0, l0); split1(s[2*ks][1], h1, l1);
                pa_h[0] = ((uint32_t)__bfloat16_as_ushort(h1) << 16) | __bfloat16_as_ushort(h0);
                pa_l[0] = ((uint32_t)__bfloat16_as_ushort(l1) << 16) | __bfloat16_as_ushort(l0);
                split1(s[2*ks][2], h0, l0); split1(s[2*ks][3], h1, l1);
                pa_h[1] = ((uint32_t)__bfloat16_as_ushort(h1) << 16) | __bfloat16_as_ushort(h0);
                pa_l[1] = ((uint32_t)__bfloat16_as_ushort(l1) << 16) | __bfloat16_as_ushort(l0);
                split1(s[2*ks+1][0], h0, l0); split1(s[2*ks+1][1], h1, l1);
                pa_h[2] = ((uint32_t)__bfloat16_as_ushort(h1) << 16) | __bfloat16_as_ushort(h0);
                pa_l[2] = ((uint32_t)__bfloat16_as_ushort(l1) << 16) | __bfloat16_as_ushort(l0);
                split1(s[2*ks+1][2], h0, l0); split1(s[2*ks+1][3], h1, l1);
                pa_h[3] = ((uint32_t)__bfloat16_as_ushort(h1) << 16) | __bfloat16_as_ushort(h0);
                pa_l[3] = ((uint32_t)__bfloat16_as_ushort(l1) << 16) | __bfloat16_as_ushort(l0);
            }
#pragma unroll
            for (int nb = 0; nb < 4; nb++) {
                const uint32_t vb = vHiB0 + ks * 16 * ALDB + nb * 32;
                uint32_t vh[4], vl[4];
                ldmx4t(vh, vb);
                ldmx4t(vl, vb + AARR);
                float* d0 = sO[nb * 2];
                float* d1 = sO[nb * 2 + 1];
                mma16816(d0, pa_h, vh[0], vh[1]);
                mma16816(d1, pa_h, vh[2], vh[3]);
                mma16816(d0, pa_h, vl[0], vl[1]);
                mma16816(d1, pa_h, vl[2], vl[3]);
                mma16816(d0, pa_l, vh[0], vh[1]);
                mma16816(d1, pa_l, vh[2], vh[3]);
            }
        }
    }

    const float inv0 = 1.0f / lrow[0];
    const float inv1 = 1.0f / lrow[1];
    const int gr0 = rowbase + qb * 128 + w * 16 + (lane >> 2);
    const int colb = h * DKV + (lane & 3) * 2;
#pragma unroll
    for (int nf = 0; nf < 8; nf++) {
        const int col = colb + nf * 8;
        *(float2*)(o + (size_t)gr0 * DDIM + col) =
            make_float2(sO[nf][0] * inv0, sO[nf][1] * inv0);
        *(float2*)(o + (size_t)(gr0 + 8) * DDIM + col) =
            make_float2(sO[nf][2] * inv1, sO[nf][3] * inv1);
    }
}

// ---------------------------------------------------------------------------
// Host
// ---------------------------------------------------------------------------
#define QSMEM128 (3 * (2*128 + 256) * LDQ)   // 122880
#define QSMEM64  (3 * (2*64  + 256) * LDQ)   // 92160

static inline void run_gemm_s8(const int8_t* A0, const int8_t* A1,
                               const int8_t* B0, const int8_t* B1,
                               const float* sA, const float* sB,
                               const float* bias, const float* res,
                               float* Cf, __nv_bfloat16* Chi, __nv_bfloat16* Clo,
                               int M, int N, int K, int gelu, int bm64)
{
    if (bm64) {
        dim3 grid(N / 128, M / 64);
        gemm_s8<64,2><<<grid, 256, QSMEM64>>>(A0, A1, B0, B1, sA, sB, bias, res,
                                              Cf, Chi, Clo, M, N, K, gelu);
    } else {
        dim3 grid(N / 128, M / 128);
        gemm_s8<128,1><<<grid, 256, QSMEM128>>>(A0, A1, B0, B1, sA, sB, bias, res,
                                                Cf, Chi, Clo, M, N, K, gelu);
    }
}

extern "C" void kernel_launch(void* const* d_in, const int* in_sizes, int n_in,
                              void* d_out, int out_size)
{
    const int*   tokens = (const int*)  d_in[0];
    const float* emb    = (const float*)d_in[1];
    const float* pos    = (const float*)d_in[2];
    const float* Wq     = (const float*)d_in[3];
    const float* bq     = (const float*)d_in[4];
    const float* Wk     = (const float*)d_in[5];
    const float* bk     = (const float*)d_in[6];
    const float* Wv     = (const float*)d_in[7];
    const float* bv     = (const float*)d_in[8];
    const float* Wo     = (const float*)d_in[9];
    const float* W1     = (const float*)d_in[10];
    const float* b1     = (const float*)d_in[11];
    const float* W2     = (const float*)d_in[12];
    const float* b2     = (const float*)d_in[13];
    const float* Wr     = (const float*)d_in[14];
    const float* br     = (const float*)d_in[15];
    float*       out    = (float*)d_out;

    float *x, *o, *h, *t, *bqkv;
    __nv_bfloat16 *qkvhi, *qkvlo;
    float *WqkvT, *WoT, *W1T, *W2T, *WrT;
    int8_t *Wqkv0, *Wqkv1, *Wo0, *Wo1, *W10, *W11, *W20, *W21, *Wr0, *Wr1;
    float *sWqkv, *sWo, *sW1, *sW2, *sWr;
    int8_t *xq0, *xq1, *oq0, *oq1, *hq0, *hq1, *tq0, *tq1;
    float *sx, *so, *sh, *st;

    cudaGetSymbolAddress((void**)&x, g_x);
    cudaGetSymbolAddress((void**)&o, g_o);
    cudaGetSymbolAddress((void**)&h, g_h);
    cudaGetSymbolAddress((void**)&t, g_t);
    cudaGetSymbolAddress((void**)&qkvhi, g_qkvhi);
    cudaGetSymbolAddress((void**)&qkvlo, g_qkvlo);
    cudaGetSymbolAddress((void**)&WqkvT, g_WqkvT);
    cudaGetSymbolAddress((void**)&WoT, g_WoT);
    cudaGetSymbolAddress((void**)&W1T, g_W1T);
    cudaGetSymbolAddress((void**)&W2T, g_W2T);
    cudaGetSymbolAddress((void**)&WrT, g_WrT);
    cudaGetSymbolAddress((void**)&bqkv, g_bqkv);
    cudaGetSymbolAddress((void**)&Wqkv0, g_Wqkv0);
    cudaGetSymbolAddress((void**)&Wqkv1, g_Wqkv1);
    cudaGetSymbolAddress((void**)&Wo0, g_Wo0);
    cudaGetSymbolAddress((void**)&Wo1, g_Wo1);
    cudaGetSymbolAddress((void**)&W10, g_W10);
    cudaGetSymbolAddress((void**)&W11, g_W11);
    cudaGetSymbolAddress((void**)&W20, g_W20);
    cudaGetSymbolAddress((void**)&W21, g_W21);
    cudaGetSymbolAddress((void**)&Wr0, g_Wr0);
    cudaGetSymbolAddress((void**)&Wr1, g_Wr1);
    cudaGetSymbolAddress((void**)&sWqkv, g_sWqkv);
    cudaGetSymbolAddress((void**)&sWo, g_sWo);
    cudaGetSymbolAddress((void**)&sW1, g_sW1);
    cudaGetSymbolAddress((void**)&sW2, g_sW2);
    cudaGetSymbolAddress((void**)&sWr, g_sWr);
    cudaGetSymbolAddress((void**)&xq0, g_xq0); cudaGetSymbolAddress((void**)&xq1, g_xq1);
    cudaGetSymbolAddress((void**)&oq0, g_oq0); cudaGetSymbolAddress((void**)&oq1, g_oq1);
    cudaGetSymbolAddress((void**)&hq0, g_hq0); cudaGetSymbolAddress((void**)&hq1, g_hq1);
    cudaGetSymbolAddress((void**)&tq0, g_tq0); cudaGetSymbolAddress((void**)&tq1, g_tq1);
    cudaGetSymbolAddress((void**)&sx, g_sx); cudaGetSymbolAddress((void**)&so, g_so);
    cudaGetSymbolAddress((void**)&sh, g_sh); cudaGetSymbolAddress((void**)&st, g_st);

    cudaFuncSetAttribute((const void*)gemm_s8<128,1>,
                         cudaFuncAttributeMaxDynamicSharedMemorySize, QSMEM128);
    cudaFuncSetAttribute((const void*)gemm_s8<64,2>,
                         cudaFuncAttributeMaxDynamicSharedMemorySize, QSMEM64);
    cudaFuncSetAttribute(attn_mma,
                         cudaFuncAttributeMaxDynamicSharedMemorySize, ASMEM);

    const size_t DD2 = (size_t)DDIM * DDIM;

    // 0: layer-0 QKV weight transpose
    tr_qkv3<<<dim3(32, 32, 3), dim3(32, 8)>>>(Wq, Wk, Wv, WqkvT, 0);
    // 1: quantize layer-0 QKV weights
    quant_rows<<<NQKV, 256>>>(WqkvT, Wqkv0, Wqkv1, sWqkv, DDIM);
    // 2: embed + bias concat
    embed_bias<<<MM + 96, 256>>>(tokens, emb, pos, x, bq, bk, bv, bqkv);
    // 3: quantize x
    quant_rows<<<MM, 256>>>(x, xq0, xq1, sx, DDIM);
    // 4: Wo transpose (all layers)
    transpose_b<<<dim3(32, 32, LLAY), dim3(32, 8)>>>(Wo, WoT, DDIM, DDIM, DD2, DD2);
    // 5: layer-0 QKV GEMM (profiled)
    run_gemm_s8(xq0, xq1, Wqkv0, Wqkv1, sx, sWqkv, bqkv, nullptr,
                nullptr, qkvhi, qkvlo, MM, NQKV, DDIM, 0, 0);

    // remaining weight prep
    tr_qkv3<<<dim3(32, 32, 21), dim3(32, 8)>>>(Wq, Wk, Wv, WqkvT, 1);
    transpose_b<<<dim3(128, 32, LLAY), dim3(32, 8)>>>(W1, W1T, DDIM, DHH,
        (size_t)DDIM*DHH, (size_t)DHH*DDIM);
    transpose_b<<<dim3(32, 128, LLAY), dim3(32, 8)>>>(W2, W2T, DHH, DDIM,
        (size_t)DHH*DDIM, (size_t)DDIM*DHH);
    transpose_b<<<dim3(8, 32, 1), dim3(32, 8)>>>(Wr, WrT, DDIM, VVOC, 0, 0);
    quant_rows<<<(LLAY-1)*NQKV, 256>>>(WqkvT + (size_t)NQKV*DDIM,
        Wqkv0 + (size_t)NQKV*DDIM, Wqkv1 + (size_t)NQKV*DDIM, sWqkv + NQKV, DDIM);
    quant_rows<<<LLAY*DDIM, 256>>>(WoT, Wo0, Wo1, sWo, DDIM);
    quant_rows<<<LLAY*DHH, 256>>>(W1T, W10, W11, sW1, DDIM);
    quant_rows<<<LLAY*DDIM, 256>>>(W2T, W20, W21, sW2, DHH);
    quant_rows<<<VVOC, 256>>>(WrT, Wr0, Wr1, sWr, DDIM);

    for (int l = 0; l < LLAY; l++) {
        if (l > 0) {
            run_gemm_s8(xq0, xq1, Wqkv0 + (size_t)l*NQKV*DDIM, Wqkv1 + (size_t)l*NQKV*DDIM,
                        sx, sWqkv + (size_t)l*NQKV, bqkv + (size_t)l*NQKV, nullptr,
                        nullptr, qkvhi, qkvlo, MM, NQKV, DDIM, 0, 0);
        }
        attn_mma<<<dim3(SSEQ/128, BB*HHH), 256, ASMEM>>>(qkvhi, qkvlo, o);
        quant_rows<<<MM, 256>>>(o, oq0, oq1, so, DDIM);
        // h = x + o @ Wo
        run_gemm_s8(oq0, oq1, Wo0 + (size_t)l*DD2, Wo1 + (size_t)l*DD2,
                    so, sWo + (size_t)l*DDIM, nullptr, x,
                    h, nullptr, nullptr, MM, DDIM, DDIM, 0, 1);
        quant_rows<<<MM, 256>>>(h, hq0, hq1, sh, DDIM);
        // t = gelu(h @ W1 + b1)
        run_gemm_s8(hq0, hq1, W10 + (size_t)l*DHH*DDIM, W11 + (size_t)l*DHH*DDIM,
                    sh, sW1 + (size_t)l*DHH, b1 + (size_t)l*DHH, nullptr,
                    t, nullptr, nullptr, MM, DHH, DDIM, 1, 0);
        quant_rows<<<MM, 256>>>(t, tq0, tq1, st, DHH);
        // x = h + t @ W2 + b2
        run_gemm_s8(tq0, tq1, W20 + (size_t)l*DDIM*DHH, W21 + (size_t)l*DDIM*DHH,
                    st, sW2 + (size_t)l*DDIM, b2 + (size_t)l*DDIM, h,
                    x, nullptr, nullptr, MM, DDIM, DHH, 0, 1);
        quant_rows<<<MM, 256>>>(x, xq0, xq1, sx, DDIM);
    }

    // LM head
    run_gemm_s8(xq0, xq1, Wr0, Wr1, sx, sWr, br, nullptr,
                out, nullptr, nullptr, MM, VVOC, DDIM, 0, 1);
}

// round 12
// speedup vs baseline: 2.6032x; 2.6032x over previous
#include <cuda_runtime.h>
#include <cuda_bf16.h>
#include <cuda_fp16.h>
#include <math.h>
#include <stdint.h>

// ---------------------------------------------------------------------------
// Problem constants
// ---------------------------------------------------------------------------
#define BB    2
#define SSEQ  1024
#define DDIM  1024
#define HHH   16
#define DKV   64
#define DHH   4096
#define LLAY  8
#define VVOC  256
#define MM    (BB*SSEQ)        // 2048
#define NQKV  3072

// ---------------------------------------------------------------------------
// Scratch (device globals: allocation-free)
// ---------------------------------------------------------------------------
__device__ float g_x   [MM*DDIM];
__device__ float g_o   [MM*DDIM];
__device__ float g_h   [MM*DDIM];
__device__ float g_t   [MM*DHH];
__device__ __nv_bfloat16 g_qkvhi[MM*NQKV], g_qkvlo[MM*NQKV];

__device__ float g_WqkvT[LLAY*NQKV*DDIM];
__device__ float g_WoT  [LLAY*DDIM*DDIM];
__device__ float g_W1T  [LLAY*DHH*DDIM];
__device__ float g_W2T  [LLAY*DDIM*DHH];
__device__ float g_WrT  [VVOC*DDIM];
__device__ float g_bqkv [LLAY*NQKV];

// ---------------------------------------------------------------------------
// Helpers
// ---------------------------------------------------------------------------
__device__ __forceinline__ uint32_t smem_u32(const void* p) {
    uint32_t a;
    asm("{ .reg .u64 t; cvta.to.shared.u64 t, %1; cvt.u32.u64 %0, t; }"
        : "=r"(a) : "l"(p));
    return a;
}

__device__ __forceinline__ void ldmx4(uint32_t* r, uint32_t addr) {
    asm volatile("ldmatrix.sync.aligned.m8n8.x4.shared.b16 {%0,%1,%2,%3}, [%4];"
        : "=r"(r[0]), "=r"(r[1]), "=r"(r[2]), "=r"(r[3]) : "r"(addr));
}

__device__ __forceinline__ void ldmx4t(uint32_t* r, uint32_t addr) {
    asm volatile("ldmatrix.sync.aligned.m8n8.x4.trans.shared.b16 {%0,%1,%2,%3}, [%4];"
        : "=r"(r[0]), "=r"(r[1]), "=r"(r[2]), "=r"(r[3]) : "r"(addr));
}

// bf16 inputs, f32 acc (attention)
__device__ __forceinline__ void mma16816(float* d, const uint32_t* a,
                                         uint32_t b0, uint32_t b1) {
    asm volatile("mma.sync.aligned.m16n8k16.row.col.f32.bf16.bf16.f32 "
        "{%0,%1,%2,%3}, {%4,%5,%6,%7}, {%8,%9}, {%0,%1,%2,%3};"
        : "+f"(d[0]), "+f"(d[1]), "+f"(d[2]), "+f"(d[3])
        : "r"(a[0]), "r"(a[1]), "r"(a[2]), "r"(a[3]), "r"(b0), "r"(b1));
}

// f16 inputs, f32 acc (GEMM main pass)
__device__ __forceinline__ void mma16816_h32(float* d, const uint32_t* a,
                                             uint32_t b0, uint32_t b1) {
    asm volatile("mma.sync.aligned.m16n8k16.row.col.f32.f16.f16.f32 "
        "{%0,%1,%2,%3}, {%4,%5,%6,%7}, {%8,%9}, {%0,%1,%2,%3};"
        : "+f"(d[0]), "+f"(d[1]), "+f"(d[2]), "+f"(d[3])
        : "r"(a[0]), "r"(a[1]), "r"(a[2]), "r"(a[3]), "r"(b0), "r"(b1));
}

// f16 inputs, f16 acc (GEMM correction pass)
__device__ __forceinline__ void mma16816_h16(uint32_t* d, const uint32_t* a,
                                             uint32_t b0, uint32_t b1) {
    asm volatile("mma.sync.aligned.m16n8k16.row.col.f16.f16.f16.f16 "
        "{%0,%1}, {%2,%3,%4,%5}, {%6,%7}, {%0,%1};"
        : "+r"(d[0]), "+r"(d[1])
        : "r"(a[0]), "r"(a[1]), "r"(a[2]), "r"(a[3]), "r"(b0), "r"(b1));
}

__device__ __forceinline__ void cp16(uint32_t dst, const void* src) {
    asm volatile("cp.async.cg.shared.global [%0], [%1], 16;"
        :: "r"(dst), "l"(src) : "memory");
}
#define CP_COMMIT() asm volatile("cp.async.commit_group;" ::: "memory")
#define CP_WAIT0()  asm volatile("cp.async.wait_group 0;" ::: "memory")

__device__ __forceinline__ float gelu_exact(float v) {
    return 0.5f * v * (1.0f + erff(v * 0.70710678118654752f));
}

#define LO_SCALE 4096.0f
#define LO_INV   (1.0f/4096.0f)

// fp16 hi-only pack
__device__ __forceinline__ uint2 pack_f4h(float4 v) {
    __half2 p0 = __halves2half2(__float2half_rn(v.x), __float2half_rn(v.y));
    __half2 p1 = __halves2half2(__float2half_rn(v.z), __float2half_rn(v.w));
    uint2 r;
    r.x = *(uint32_t*)&p0;
    r.y = *(uint32_t*)&p1;
    return r;
}

// fp16 split: hi = f16(v), lo = f16((v-hi)*4096)
__device__ __forceinline__ void split_f4h(float4 v, uint2& hi, uint2& lo) {
    __half h0 = __float2half_rn(v.x);
    __half h1 = __float2half_rn(v.y);
    __half h2 = __float2half_rn(v.z);
    __half h3 = __float2half_rn(v.w);
    __half l0 = __float2half_rn((v.x - __half2float(h0)) * LO_SCALE);
    __half l1 = __float2half_rn((v.y - __half2float(h1)) * LO_SCALE);
    __half l2 = __float2half_rn((v.z - __half2float(h2)) * LO_SCALE);
    __half l3 = __float2half_rn((v.w - __half2float(h3)) * LO_SCALE);
    __half2 hp0 = __halves2half2(h0, h1), hp1 = __halves2half2(h2, h3);
    __half2 lp0 = __halves2half2(l0, l1), lp1 = __halves2half2(l2, l3);
    hi.x = *(uint32_t*)&hp0; hi.y = *(uint32_t*)&hp1;
    lo.x = *(uint32_t*)&lp0; lo.y = *(uint32_t*)&lp1;
}

__device__ __forceinline__ void split1(float v, __nv_bfloat16& hi, __nv_bfloat16& lo) {
    hi = __float2bfloat16(v);
    lo = __float2bfloat16(v - __bfloat162float(hi));
}

// ---------------------------------------------------------------------------
// GEMM: C = act(A @ Bt^T + bias) + res; fp32 in, fp16 split in-kernel.
// 2-pass: D = Ahi*Bhi (f32 acc) + Ahi*Blo' (f16 acc, Blo pre-scaled 2^12).
// BM in {128, 64}; BN = 128; BK = 32; 8 warps; double-buffered smem.
// ---------------------------------------------------------------------------
#define LDB 80

template<int BM, int MINB>
__global__ void __launch_bounds__(256, MINB)
gemm_mma(const float* __restrict__ A, const float* __restrict__ Bt,
         const float* __restrict__ bias, const float* __restrict__ res,
         float* __restrict__ Cf,
         __nv_bfloat16* __restrict__ Chi, __nv_bfloat16* __restrict__ Clo,
         int M, int N, int K, int gelu)
{
    constexpr int MT      = BM / 32;
    constexpr int AP      = BM / 32;
    constexpr int OFF_BHI = BM * LDB;
    constexpr int OFF_BLO = (BM + 128) * LDB;
    constexpr int STAGE   = (BM + 256) * LDB;

    extern __shared__ char sm[];
    const uint32_t smb = smem_u32(sm);

    const int tid  = threadIdx.x;
    const int lane = tid & 31;
    const int wid  = tid >> 5;
    const int wr   = wid >> 2;
    const int wc   = wid & 3;
    const int m0   = blockIdx.y * BM;
    const int n0   = blockIdx.x * 128;

    const int sc4  = tid & 7;
    const int srow = tid >> 3;
    const float* aP = A  + (size_t)(m0 + srow) * K + sc4 * 4;
    const float* bP = Bt + (size_t)(n0 + srow) * K + sc4 * 4;

    float acc[MT][4][4];
    uint32_t corr[MT][4][2];
#pragma unroll
    for (int i = 0; i < MT; i++)
#pragma unroll
        for (int j = 0; j < 4; j++) {
#pragma unroll
            for (int q = 0; q < 4; q++) acc[i][j][q] = 0.0f;
            corr[i][j][0] = 0u; corr[i][j][1] = 0u;
        }

    float4 ra[AP], rb[4];
#pragma unroll
    for (int p = 0; p < AP; p++)
        ra[p] = __ldg((const float4*)(aP + (size_t)p * 32 * K));
#pragma unroll
    for (int p = 0; p < 4; p++)
        rb[p] = __ldg((const float4*)(bP + (size_t)p * 32 * K));
    {
        char* sp = sm;
#pragma unroll
        for (int p = 0; p < AP; p++) {
            uint32_t off = (uint32_t)((srow + p * 32) * LDB + sc4 * 8);
            *(uint2*)(sp + off) = pack_f4h(ra[p]);
        }
#pragma unroll
        for (int p = 0; p < 4; p++) {
            uint32_t off = (uint32_t)((srow + p * 32) * LDB + sc4 * 8);
            uint2 hi, lo;
            split_f4h(rb[p], hi, lo);
            *(uint2*)(sp + OFF_BHI + off) = hi;
            *(uint2*)(sp + OFF_BLO + off) = lo;
        }
    }
    __syncthreads();

    const int nIt = K >> 5;
    for (int it = 0; it < nIt; ++it) {
        const int cur = it & 1;

        if (it + 1 < nIt) {
#pragma unroll
            for (int p = 0; p < AP; p++)
                ra[p] = __ldg((const float4*)(aP + (it + 1) * 32 + (size_t)p * 32 * K));
#pragma unroll
            for (int p = 0; p < 4; p++)
                rb[p] = __ldg((const float4*)(bP + (it + 1) * 32 + (size_t)p * 32 * K));
        }

        const uint32_t stage = smb + cur * STAGE;
        const uint32_t aHiB = stage
            + (uint32_t)((wr * (BM/2) + (lane & 15)) * LDB + (lane >> 4) * 16);
        const uint32_t bHiB = stage + OFF_BHI + (uint32_t)((wc * 32 + lane) * LDB);

#pragma unroll
        for (int kc = 0; kc < 2; kc++) {
            uint32_t ahi[MT][4];
            uint32_t bh0[4], bh1[4], bl0[4], bl1[4];
#pragma unroll
            for (int mt = 0; mt < MT; mt++)
                ldmx4(ahi[mt], aHiB + mt * 16 * LDB + kc * 32);
            ldmx4(bh0, bHiB + kc * 32);
            ldmx4(bh1, bHiB + kc * 32 + 16);
            ldmx4(bl0, bHiB + (OFF_BLO - OFF_BHI) + kc * 32);
            ldmx4(bl1, bHiB + (OFF_BLO - OFF_BHI) + kc * 32 + 16);

            // pass 1: hi*hi -> f32
#pragma unroll
            for (int mt = 0; mt < MT; mt++)
#pragma unroll
                for (int nt = 0; nt < 4; nt++)
                    mma16816_h32(acc[mt][nt], ahi[mt], bh0[nt], bh1[nt]);
            // pass 2: hi*lo' -> f16 corr
#pragma unroll
            for (int mt = 0; mt < MT; mt++)
#pragma unroll
                for (int nt = 0; nt < 4; nt++)
                    mma16816_h16(corr[mt][nt], ahi[mt], bl0[nt], bl1[nt]);
        }

        if (it + 1 < nIt) {
            char* sp = sm + ((it + 1) & 1) * STAGE;
#pragma unroll
            for (int p = 0; p < AP; p++) {
                uint32_t off = (uint32_t)((srow + p * 32) * LDB + sc4 * 8);
                *(uint2*)(sp + off) = pack_f4h(ra[p]);
            }
#pragma unroll
            for (int p = 0; p < 4; p++) {
                uint32_t off = (uint32_t)((srow + p * 32) * LDB + sc4 * 8);
                uint2 hi, lo;
                split_f4h(rb[p], hi, lo);
                *(uint2*)(sp + OFF_BHI + off) = hi;
                *(uint2*)(sp + OFF_BLO + off) = lo;
            }
        }
        __syncthreads();
    }

    // merge corrections
#pragma unroll
    for (int mt = 0; mt < MT; mt++)
#pragma unroll
        for (int nt = 0; nt < 4; nt++) {
            __half2 c01 = *(__half2*)&corr[mt][nt][0];
            __half2 c23 = *(__half2*)&corr[mt][nt][1];
            acc[mt][nt][0] += __low2float(c01)  * LO_INV;
            acc[mt][nt][1] += __high2float(c01) * LO_INV;
            acc[mt][nt][2] += __low2float(c23)  * LO_INV;
            acc[mt][nt][3] += __high2float(c23) * LO_INV;
        }

    // ---- epilogue ----
    const int er = m0 + wr * (BM/2) + (lane >> 2);
    const int ec = n0 + wc * 32 + (lane & 3) * 2;
#pragma unroll
    for (int mt = 0; mt < MT; mt++) {
#pragma unroll
        for (int half = 0; half < 2; half++) {
            const int row = er + mt * 16 + half * 8;
            const size_t rb2 = (size_t)row * N;
            const float* rrow = res ? res + rb2 : nullptr;
#pragma unroll
            for (int nt = 0; nt < 4; nt++) {
                const int col = ec + nt * 8;
                float v0 = acc[mt][nt][half * 2 + 0];
                float v1 = acc[mt][nt][half * 2 + 1];
                if (bias) { v0 += bias[col]; v1 += bias[col + 1]; }
                if (gelu) { v0 = gelu_exact(v0); v1 = gelu_exact(v1); }
                if (rrow) { v0 += rrow[col]; v1 += rrow[col + 1]; }
                if (Cf) *(float2*)(Cf + rb2 + col) = make_float2(v0, v1);
                if (Chi) {
                    __nv_bfloat16 h0, l0, h1, l1;
                    split1(v0, h0, l0);
                    split1(v1, h1, l1);
                    *(__nv_bfloat162*)(Chi + rb2 + col) = __nv_bfloat162(h0, h1);
                    *(__nv_bfloat162*)(Clo + rb2 + col) = __nv_bfloat162(l0, l1);
                }
            }
        }
    }
}

// ---------------------------------------------------------------------------
// Batched transposes
// ---------------------------------------------------------------------------
__global__ void tr_qkv3(const float* __restrict__ Wq, const float* __restrict__ Wk,
                        const float* __restrict__ Wv, float* __restrict__ dst,
                        int l0)
{
    __shared__ float t[32][33];
    const int z = blockIdx.z;
    const int l = l0 + z / 3;
    const int which = z % 3;
    const float* src = (which == 0 ? Wq : which == 1 ? Wk : Wv)
                     + (size_t)l * DDIM * DDIM;
    float* d = dst + (size_t)l * NQKV * DDIM + (size_t)which * DDIM * DDIM;
    const int k0 = blockIdx.y * 32, n0 = blockIdx.x * 32;
    const int tx = threadIdx.x, ty = threadIdx.y;
#pragma unroll
    for (int i = 0; i < 32; i += 8)
        t[ty + i][tx] = src[(size_t)(k0 + ty + i) * DDIM + n0 + tx];
    __syncthreads();
#pragma unroll
    for (int i = 0; i < 32; i += 8)
        d[(size_t)(n0 + ty + i) * DDIM + k0 + tx] = t[tx][ty + i];
}

__global__ void transpose_b(const float* __restrict__ src, float* __restrict__ dst,
                            int K, int N, size_t sstr, size_t dstr)
{
    __shared__ float t[32][33];
    const int l = blockIdx.z;
    src += (size_t)l * sstr;
    dst += (size_t)l * dstr;
    const int k0 = blockIdx.y * 32, n0 = blockIdx.x * 32;
    const int tx = threadIdx.x, ty = threadIdx.y;
#pragma unroll
    for (int i = 0; i < 32; i += 8)
        t[ty + i][tx] = src[(size_t)(k0 + ty + i) * N + n0 + tx];
    __syncthreads();
#pragma unroll
    for (int i = 0; i < 32; i += 8)
        dst[(size_t)(n0 + ty + i) * K + k0 + tx] = t[tx][ty + i];
}

// ---------------------------------------------------------------------------
// Fused embedding + bias concat
// ---------------------------------------------------------------------------
__global__ void embed_bias(const int* __restrict__ tokens,
                           const float* __restrict__ emb,
                           const float* __restrict__ pos,
                           float* __restrict__ x,
                           const float* __restrict__ bq, const float* __restrict__ bk,
                           const float* __restrict__ bv, float* __restrict__ bqkv)
{
    if (blockIdx.x < MM) {
        int i = blockIdx.x;
        int s = i & (SSEQ - 1);
        int t = tokens[i];
        const float4* e4 = (const float4*)(emb + (size_t)t * DDIM);
        const float4* p4 = (const float4*)(pos + (size_t)s * DDIM);
        float4*       x4 = (float4*)(x + (size_t)i * DDIM);
        int d = threadIdx.x;
        float4 a = e4[d], b = p4[d];
        x4[d] = make_float4(a.x + b.x, a.y + b.y, a.z + b.z, a.w + b.w);
    } else {
        int e = (blockIdx.x - MM) * 256 + threadIdx.x;
        int l = e / NQKV;
        int i = e - l * NQKV;
        float v;
        if (i < 1024)       v = bq[l * DDIM + i];
        else if (i < 2048)  v = bk[l * DDIM + i - 1024];
        else                v = bv[l * DDIM + i - 2048];
        bqkv[e] = v;
    }
}

// ---------------------------------------------------------------------------
// Tensor-core flash attention (R10-proven, bf16x3), fp32 output
// ---------------------------------------------------------------------------
#define ALDB  144
#define AQHI  0
#define AQLO  18432
#define AKHI  36864
#define AARR  9216
#define ASMEM 73728

__global__ void __launch_bounds__(256, 2)
attn_mma(const __nv_bfloat16* __restrict__ qkvhi,
         const __nv_bfloat16* __restrict__ qkvlo,
         float* __restrict__ o)
{
    extern __shared__ char sm[];
    const uint32_t smb = smem_u32(sm);

    const int tid  = threadIdx.x;
    const int lane = tid & 31;
    const int w    = tid >> 5;
    const int qb   = blockIdx.x;
    const int bh   = blockIdx.y;
    const int b    = bh >> 4;
    const int h    = bh & 15;
    const int rowbase = b * SSEQ;
    const int qc = h * DKV, kc = 1024 + h * DKV, vc = 2048 + h * DKV;

    {
        const int ch  = tid & 7;
        const int wh  = (tid >> 3) & 1;
        const __nv_bfloat16* src = (wh ? qkvlo : qkvhi);
        const uint32_t dstb = smb + (wh ? AQLO : AQHI) + ch * 16;
#pragma unroll
        for (int i = 0; i < 8; i++) {
            const int r = i * 16 + (tid >> 4);
            cp16(dstb + r * ALDB,
                 src + (size_t)(rowbase + qb * 128 + r) * NQKV + qc + ch * 8);
        }
        CP_COMMIT();
    }

    float sO[8][4];
#pragma unroll
    for (int i = 0; i < 8; i++)
#pragma unroll
        for (int q = 0; q < 4; q++) sO[i][q] = 0.0f;
    float mrow[2] = { -INFINITY, -INFINITY };
    float lrow[2] = { 0.0f, 0.0f };

    const int ch  = tid & 7;
    const int arr = (tid >> 3) & 3;
    const __nv_bfloat16* kvsrc =
        (arr == 0) ? qkvhi : (arr == 1) ? qkvlo : (arr == 2) ? qkvhi : qkvlo;
    const int kvcol = (arr < 2) ? kc : vc;
    const uint32_t kvdstb = smb + AKHI + arr * AARR + ch * 16;

    const int ntile = 2 * (qb + 1);
    for (int kt = 0; kt < ntile; kt++) {
        __syncthreads();
        {
#pragma unroll
            for (int i = 0; i < 8; i++) {
                const int r = i * 8 + (tid >> 5);
                cp16(kvdstb + r * ALDB,
                     kvsrc + (size_t)(rowbase + kt * 64 + r) * NQKV + kvcol + ch * 8);
            }
            CP_COMMIT();
        }
        CP_WAIT0();
        __syncthreads();

        float s[8][4];
#pragma unroll
        for (int i = 0; i < 8; i++)
#pragma unroll
            for (int q = 0; q < 4; q++) s[i][q] = 0.0f;

        const uint32_t qHiB = smb + AQHI
            + (uint32_t)((w * 16 + (lane & 15)) * ALDB + (lane >> 4) * 16);
        const uint32_t kHiB0 = smb + AKHI + (uint32_t)(lane * ALDB);

#pragma unroll
        for (int ks = 0; ks < 4; ks++) {
            uint32_t aH[4], aL[4];
            ldmx4(aH, qHiB + ks * 32);
            ldmx4(aL, qHiB + (AQLO - AQHI) + ks * 32);
#pragma unroll
            for (int nb = 0; nb < 2; nb++) {
                const uint32_t kb = kHiB0 + nb * 32 * ALDB + ks * 32;
                uint32_t bh0[4], bh1[4], bl0[4], bl1[4];
                ldmx4(bh0, kb);
                ldmx4(bh1, kb + 16);
                ldmx4(bl0, kb + AARR);
                ldmx4(bl1, kb + AARR + 16);
#pragma unroll
                for (int nt = 0; nt < 4; nt++)
                    mma16816(s[nb * 4 + nt], aH, bh0[nt], bh1[nt]);
#pragma unroll
                for (int nt = 0; nt < 4; nt++)
                    mma16816(s[nb * 4 + nt], aH, bl0[nt], bl1[nt]);
#pragma unroll
                for (int nt = 0; nt < 4; nt++)
                    mma16816(s[nb * 4 + nt], aL, bh0[nt], bh1[nt]);
            }
        }

        const int r0 = qb * 128 + w * 16 + (lane >> 2);
        const int c0 = kt * 64 + (lane & 3) * 2;
#pragma unroll
        for (int nf = 0; nf < 8; nf++) {
            const int col = c0 + nf * 8;
#pragma unroll
            for (int q = 0; q < 4; q++) {
                const int row = r0 + (q >> 1) * 8;
                const int cc  = col + (q & 1);
                float v = s[nf][q] * 0.125f;
                s[nf][q] = (cc > row) ? -INFINITY : v;
            }
        }

        float mx0 = s[0][0], mx1 = s[0][2];
#pragma unroll
        for (int nf = 0; nf < 8; nf++) {
            mx0 = fmaxf(mx0, fmaxf(s[nf][0], s[nf][1]));
            mx1 = fmaxf(mx1, fmaxf(s[nf][2], s[nf][3]));
        }
        mx0 = fmaxf(mx0, __shfl_xor_sync(0xffffffffu, mx0, 1));
        mx0 = fmaxf(mx0, __shfl_xor_sync(0xffffffffu, mx0, 2));
        mx1 = fmaxf(mx1, __shfl_xor_sync(0xffffffffu, mx1, 1));
        mx1 = fmaxf(mx1, __shfl_xor_sync(0xffffffffu, mx1, 2));

        const float mn0 = fmaxf(mrow[0], mx0);
        const float mn1 = fmaxf(mrow[1], mx1);
        const float co0 = __expf(mrow[0] - mn0);
        const float co1 = __expf(mrow[1] - mn1);
        lrow[0] *= co0; lrow[1] *= co1;
#pragma unroll
        for (int nf = 0; nf < 8; nf++) {
            sO[nf][0] *= co0; sO[nf][1] *= co0;
            sO[nf][2] *= co1; sO[nf][3] *= co1;
        }
        float su0 = 0.0f, su1 = 0.0f;
#pragma unroll
        for (int nf = 0; nf < 8; nf++) {
            s[nf][0] = __expf(s[nf][0] - mn0); su0 += s[nf][0];
            s[nf][1] = __expf(s[nf][1] - mn0); su0 += s[nf][1];
            s[nf][2] = __expf(s[nf][2] - mn1); su1 += s[nf][2];
            s[nf][3] = __expf(s[nf][3] - mn1); su1 += s[nf][3];
        }
        su0 += __shfl_xor_sync(0xffffffffu, su0, 1);
        su0 += __shfl_xor_sync(0xffffffffu, su0, 2);
        su1 += __shfl_xor_sync(0xffffffffu, su1, 1);
        su1 += __shfl_xor_sync(0xffffffffu, su1, 2);
        lrow[0] += su0; lrow[1] += su1;
        mrow[0] = mn0; mrow[1] = mn1;

        const uint32_t vHiB0 = smb + AKHI + 2 * AARR
            + (uint32_t)((lane & 15) * ALDB + (lane >> 4) * 16);
#pragma unroll
        for (int ks = 0; ks < 4; ks++) {
            uint32_t pa_h[4], pa_l[4];
            {
                __nv_bfloat16 h0, l0, h1, l1;
                split1(s[2*ks][0], h0, l0); split1(s[2*ks][1], h1, l1);
                pa_h[0] = ((uint32_t)__bfloat16_as_ushort(h1) << 16) | __bfloat16_as_ushort(h0);
                pa_l[0] = ((uint32_t)__bfloat16_as_ushort(l1) << 16) | __bfloat16_as_ushort(l0);
                split1(s[2*ks][2], h0, l0); split1(s[2*ks][3], h1, l1);
                pa_h[1] = ((uint32_t)__bfloat16_as_ushort(h1) << 16) | __bfloat16_as_ushort(h0);
                pa_l[1] = ((uint32_t)__bfloat16_as_ushort(l1) << 16) | __bfloat16_as_ushort(l0);
                split1(s[2*ks+1][0], h0, l0); split1(s[2*ks+1][1], h1, l1);
                pa_h[2] = ((uint32_t)__bfloat16_as_ushort(h1) << 16) | __bfloat16_as_ushort(h0);
                pa_l[2] = ((uint32_t)__bfloat16_as_ushort(l1) << 16) | __bfloat16_as_ushort(l0);
                split1(s[2*ks+1][2], h0, l0); split1(s[2*ks+1][3], h1, l1);
                pa_h[3] = ((uint32_t)__bfloat16_as_ushort(h1) << 16) | __bfloat16_as_ushort(h0);
                pa_l[3] = ((uint32_t)__bfloat16_as_ushort(l1) << 16) | __bfloat16_as_ushort(l0);
            }
#pragma unroll
            for (int nb = 0; nb < 4; nb++) {
                const uint32_t vb = vHiB0 + ks * 16 * ALDB + nb * 32;
                uint32_t vh[4], vl[4];
                ldmx4t(vh, vb);
                ldmx4t(vl, vb + AARR);
                float* d0 = sO[nb * 2];
                float* d1 = sO[nb * 2 + 1];
                mma16816(d0, pa_h, vh[0], vh[1]);
                mma16816(d1, pa_h, vh[2], vh[3]);
                mma16816(d0, pa_h, vl[0], vl[1]);
                mma16816(d1, pa_h, vl[2], vl[3]);
                mma16816(d0, pa_l, vh[0], vh[1]);
                mma16816(d1, pa_l, vh[2], vh[3]);
            }
        }
    }

    const float inv0 = 1.0f / lrow[0];
    const float inv1 = 1.0f / lrow[1];
    const int gr0 = rowbase + qb * 128 + w * 16 + (lane >> 2);
    const int colb = h * DKV + (lane & 3) * 2;
#pragma unroll
    for (int nf = 0; nf < 8; nf++) {
        const int col = colb + nf * 8;
        *(float2*)(o + (size_t)gr0 * DDIM + col) =
            make_float2(sO[nf][0] * inv0, sO[nf][1] * inv0);
        *(float2*)(o + (size_t)(gr0 + 8) * DDIM + col) =
            make_float2(sO[nf][2] * inv1, sO[nf][3] * inv1);
    }
}

// ---------------------------------------------------------------------------
// Host
// ---------------------------------------------------------------------------
#define GSMEM128 (2 * (128 + 256) * LDB)   // 61440
#define GSMEM64  (2 * (64  + 256) * LDB)   // 51200

static inline void run_gemm(const float* A, const float* Bt, const float* bias,
                            const float* res, float* Cf,
                            __nv_bfloat16* Chi, __nv_bfloat16* Clo,
                            int M, int N, int K, int gelu, int bm64)
{
    if (bm64) {
        dim3 grid(N / 128, M / 64);
        gemm_mma<64,2><<<grid, 256, GSMEM64>>>(A, Bt, bias, res, Cf, Chi, Clo,
                                               M, N, K, gelu);
    } else {
        dim3 grid(N / 128, M / 128);
        gemm_mma<128,1><<<grid, 256, GSMEM128>>>(A, Bt, bias, res, Cf, Chi, Clo,
                                                 M, N, K, gelu);
    }
}

extern "C" void kernel_launch(void* const* d_in, const int* in_sizes, int n_in,
                              void* d_out, int out_size)
{
    const int*   tokens = (const int*)  d_in[0];
    const float* emb    = (const float*)d_in[1];
    const float* pos    = (const float*)d_in[2];
    const float* Wq     = (const float*)d_in[3];
    const float* bq     = (const float*)d_in[4];
    const float* Wk     = (const float*)d_in[5];
    const float* bk     = (const float*)d_in[6];
    const float* Wv     = (const float*)d_in[7];
    const float* bv     = (const float*)d_in[8];
    const float* Wo     = (const float*)d_in[9];
    const float* W1     = (const float*)d_in[10];
    const float* b1     = (const float*)d_in[11];
    const float* W2     = (const float*)d_in[12];
    const float* b2     = (const float*)d_in[13];
    const float* Wr     = (const float*)d_in[14];
    const float* br     = (const float*)d_in[15];
    float*       out    = (float*)d_out;

    float *x, *o, *h, *t, *bqkv;
    __nv_bfloat16 *qkvhi, *qkvlo;
    float *WqkvT, *WoT, *W1T, *W2T, *WrT;
    cudaGetSymbolAddress((void**)&x,     g_x);
    cudaGetSymbolAddress((void**)&o,     g_o);
    cudaGetSymbolAddress((void**)&h,     g_h);
    cudaGetSymbolAddress((void**)&t,     g_t);
    cudaGetSymbolAddress((void**)&qkvhi, g_qkvhi);
    cudaGetSymbolAddress((void**)&qkvlo, g_qkvlo);
    cudaGetSymbolAddress((void**)&WqkvT, g_WqkvT);
    cudaGetSymbolAddress((void**)&WoT,   g_WoT);
    cudaGetSymbolAddress((void**)&W1T,   g_W1T);
    cudaGetSymbolAddress((void**)&W2T,   g_W2T);
    cudaGetSymbolAddress((void**)&WrT,   g_WrT);
    cudaGetSymbolAddress((void**)&bqkv,  g_bqkv);

    cudaFuncSetAttribute((const void*)gemm_mma<128,1>,
                         cudaFuncAttributeMaxDynamicSharedMemorySize, GSMEM128);
    cudaFuncSetAttribute((const void*)gemm_mma<64,2>,
                         cudaFuncAttributeMaxDynamicSharedMemorySize, GSMEM64);
    cudaFuncSetAttribute(attn_mma,
                         cudaFuncAttributeMaxDynamicSharedMemorySize, ASMEM);

    const size_t DD2 = (size_t)DDIM * DDIM;

    // launch 0: layer-0 QKV weight transpose
    tr_qkv3<<<dim3(32, 32, 3), dim3(32, 8)>>>(Wq, Wk, Wv, WqkvT, 0);
    // launch 1: Wo transpose, all layers
    transpose_b<<<dim3(32, 32, LLAY), dim3(32, 8)>>>(Wo, WoT, DDIM, DDIM, DD2, DD2);
    // launch 2: embed + bias concat
    embed_bias<<<MM + 96, 256>>>(tokens, emb, pos, x, bq, bk, bv, bqkv);
    // launch 3: layer-0 QKV GEMM
    run_gemm(x, WqkvT, bqkv, nullptr, nullptr, qkvhi, qkvlo, MM, NQKV, DDIM, 0, 0);
    // launch 4: layer-0 attention
    attn_mma<<<dim3(SSEQ/128, BB*HHH), 256, ASMEM>>>(qkvhi, qkvlo, o);
    // launch 5: layer-0 Wo GEMM (BM=64)
    run_gemm(o, WoT, nullptr, x, h, nullptr, nullptr, MM, DDIM, DDIM, 0, 1);

    // remaining weight prep
    tr_qkv3<<<dim3(32, 32, 21), dim3(32, 8)>>>(Wq, Wk, Wv, WqkvT, 1);
    transpose_b<<<dim3(128, 32, LLAY), dim3(32, 8)>>>(W1, W1T, DDIM, DHH,
                                                      (size_t)DDIM*DHH, (size_t)DHH*DDIM);
    transpose_b<<<dim3(32, 128, LLAY), dim3(32, 8)>>>(W2, W2T, DHH, DDIM,
                                                      (size_t)DHH*DDIM, (size_t)DDIM*DHH);
    transpose_b<<<dim3(8, 32, 1), dim3(32, 8)>>>(Wr, WrT, DDIM, VVOC, 0, 0);

    // layer-0 MLP
    run_gemm(h, W1T, b1, nullptr, t, nullptr, nullptr, MM, DHH, DDIM, 1, 0);
    run_gemm(t, W2T, b2, h, x, nullptr, nullptr, MM, DDIM, DHH, 0, 1);

    for (int l = 1; l < LLAY; l++) {
        const float* woT = WoT + (size_t)l*DD2;
        const float* w1T = W1T + (size_t)l*DHH*DDIM;
        const float* w2T = W2T + (size_t)l*DDIM*DHH;

        run_gemm(x, WqkvT + (size_t)l*NQKV*DDIM, bqkv + (size_t)l*NQKV, nullptr,
                 nullptr, qkvhi, qkvlo, MM, NQKV, DDIM, 0, 0);
        attn_mma<<<dim3(SSEQ/128, BB*HHH), 256, ASMEM>>>(qkvhi, qkvlo, o);
        run_gemm(o, woT, nullptr, x, h, nullptr, nullptr, MM, DDIM, DDIM, 0, 1);
        run_gemm(h, w1T, b1 + (size_t)l*DHH, nullptr, t, nullptr, nullptr,
                 MM, DHH, DDIM, 1, 0);
        run_gemm(t, w2T, b2 + (size_t)l*DDIM, h, x, nullptr, nullptr,
                 MM, DDIM, DHH, 0, 1);
    }

    // LM head (BM=64)
    run_gemm(x, WrT, br, nullptr, out, nullptr, nullptr, MM, VVOC, DDIM, 0, 1);
}